// round 7
// baseline (speedup 1.0000x reference)
#include <cuda_runtime.h>

#define NG 128
#define FEAT 16
#define WIDTH 64
#define NUM_POS 3
#define IN_MLP 25          // FEAT + NUM_POS*3
#define NPAIR 13           // ceil(25/2) packed input pairs
#define MAX_PTS 262144
#define NB 4096            // 16^3 buckets of 8^3 grid cells
#define GATHER_BLOCKS 304  // 2 per SM x 152 SMs (persistent)

// ---- scratch (device globals per harness rules) ----
__device__ float  g_feat[MAX_PTS * FEAT];  // features, sorted order (16 MB)
__device__ float4 g_xs[MAX_PTS];           // (x,y,z, orig-idx-bits), sorted order
__device__ int    g_hist[NB];
__device__ int    g_base[NB];
__device__ int    g_key [MAX_PTS];
__device__ int    g_rank[MAX_PTS];

// ---- packed f32x2 helpers (sm_10x) ----
__device__ __forceinline__ unsigned long long pack2(float a, float b) {
    unsigned long long r;
    asm("mov.b64 %0, {%1, %2};" : "=l"(r) : "f"(a), "f"(b));
    return r;
}
__device__ __forceinline__ void unpack2(unsigned long long v, float& a, float& b) {
    asm("mov.b64 {%0, %1}, %2;" : "=f"(a), "=f"(b) : "l"(v));
}
__device__ __forceinline__ unsigned long long fma2(unsigned long long a,
                                                   unsigned long long b,
                                                   unsigned long long c) {
    unsigned long long d;
    asm("fma.rn.f32x2 %0, %1, %2, %3;" : "=l"(d) : "l"(a), "l"(b), "l"(c));
    return d;
}

__device__ __forceinline__ void cubic_w(float t, float w[4]) {
    float t2 = t * t, t3 = t2 * t;
    w[0] = 0.5f * (-t3 + 2.0f * t2 - t);
    w[1] = 0.5f * (3.0f * t3 - 5.0f * t2 + 2.0f);
    w[2] = 0.5f * (-3.0f * t3 + 4.0f * t2 + t);
    w[3] = 0.5f * (t3 - t2);
}

// ================= sorting passes =================

__global__ __launch_bounds__(256) void zero_hist_kernel() {
    int i = blockIdx.x * 256 + threadIdx.x;
    if (i < NB) g_hist[i] = 0;
}

__global__ __launch_bounds__(256) void hist_kernel(const float* __restrict__ x, int npts) {
    int pt = blockIdx.x * 256 + threadIdx.x;
    if (pt >= npts) return;
    int ix = (int)floorf(x[3 * pt + 0] * 127.0f);
    int iy = (int)floorf(x[3 * pt + 1] * 127.0f);
    int iz = (int)floorf(x[3 * pt + 2] * 127.0f);
    ix = min(max(ix, 0), 127); iy = min(max(iy, 0), 127); iz = min(max(iz, 0), 127);
    int key = ((ix >> 3) << 8) | ((iy >> 3) << 4) | (iz >> 3);
    int rank = atomicAdd(&g_hist[key], 1);
    g_key[pt] = key;
    g_rank[pt] = rank;
}

__global__ __launch_bounds__(1024) void scan_kernel() {
    __shared__ int s[1024];
    int tid = threadIdx.x;
    int base = tid * 4;
    int local[4];
    int sum = 0;
    #pragma unroll
    for (int i = 0; i < 4; i++) { local[i] = sum; sum += g_hist[base + i]; }
    s[tid] = sum;
    __syncthreads();
    for (int off = 1; off < 1024; off <<= 1) {
        int v = (tid >= off) ? s[tid - off] : 0;
        __syncthreads();
        s[tid] += v;
        __syncthreads();
    }
    int chunk = (tid > 0) ? s[tid - 1] : 0;
    #pragma unroll
    for (int i = 0; i < 4; i++) g_base[base + i] = chunk + local[i];
}

// Scatter: write (x,y,z,orig-idx) into sorted slots.
__global__ __launch_bounds__(256) void scatter_kernel(const float* __restrict__ x, int npts) {
    int pt = blockIdx.x * 256 + threadIdx.x;
    if (pt >= npts) return;
    int pos = g_base[g_key[pt]] + g_rank[pt];
    g_xs[pos] = make_float4(x[3 * pt + 0], x[3 * pt + 1], x[3 * pt + 2],
                            __int_as_float(pt));
}

// ================= tricubic gather: persistent blocks, bucket-local L1 reuse =
// 512 threads/block, 16 lanes/pt (c = z-tap, fg = float4 group), 32 pts/iter.
// One block owns whole buckets serially -> the bucket footprint (11^3 nodes,
// ~85 KB) stays L1-resident across all its ~64 points. 2 blocks/SM -> 170 KB.
__global__ __launch_bounds__(512) void gather_kernel(
    const float* __restrict__ grid)
{
    int sub   = threadIdx.x & 15;
    int c     = sub >> 2;
    int fg    = sub & 3;
    int group = threadIdx.x >> 4;    // 0..31

    for (int b = blockIdx.x; b < NB; b += GATHER_BLOCKS) {
        int cnt = g_hist[b];
        int start = g_base[b];
        for (int p0 = 0; p0 < cnt; p0 += 32) {
            int myp = p0 + group;
            bool valid = (myp < cnt);
            int spt = start + (valid ? myp : cnt - 1);

            float4 xp = __ldg(&g_xs[spt]);   // broadcast across the 16 lanes
            float ux = xp.x * 127.0f;
            float uy = xp.y * 127.0f;
            float uz = xp.z * 127.0f;
            float fx = floorf(ux), fy = floorf(uy), fz = floorf(uz);
            float tx = ux - fx, ty = uy - fy, tz = uz - fz;
            int ix0 = (int)fx, iy0 = (int)fy, iz0 = (int)fz;

            float wx[4], wy[4], wz[4];
            cubic_w(tx, wx);
            cubic_w(ty, wy);
            cubic_w(tz, wz);
            float wzc = wz[c];
            int zi = min(max(iz0 + c - 1, 0), NG - 1);

            float4 acc = make_float4(0.f, 0.f, 0.f, 0.f);
            #pragma unroll
            for (int a = 0; a < 4; a++) {
                int xi = min(max(ix0 + a - 1, 0), NG - 1);
                const float* gx = grid + (size_t)xi * (NG * NG * FEAT);
                float wxa = wx[a];
                #pragma unroll
                for (int bb = 0; bb < 4; bb++) {
                    int yi = min(max(iy0 + bb - 1, 0), NG - 1);
                    float w = wxa * wy[bb] * wzc;
                    const float4* gp =
                        reinterpret_cast<const float4*>(gx + (yi * NG + zi) * FEAT) + fg;
                    float4 v = __ldg(gp);
                    acc.x += w * v.x;
                    acc.y += w * v.y;
                    acc.z += w * v.z;
                    acc.w += w * v.w;
                }
            }

            const unsigned m = 0xFFFFFFFFu;
            acc.x += __shfl_xor_sync(m, acc.x, 4);
            acc.y += __shfl_xor_sync(m, acc.y, 4);
            acc.z += __shfl_xor_sync(m, acc.z, 4);
            acc.w += __shfl_xor_sync(m, acc.w, 4);
            acc.x += __shfl_xor_sync(m, acc.x, 8);
            acc.y += __shfl_xor_sync(m, acc.y, 8);
            acc.z += __shfl_xor_sync(m, acc.z, 8);
            acc.w += __shfl_xor_sync(m, acc.w, 8);

            if (valid && c == 0)
                reinterpret_cast<float4*>(g_feat)[spt * 4 + fg] = acc;
        }
    }
}

// ================= MLP: 1 point/thread, INPUT pairs via f32x2 ===============
__global__ __launch_bounds__(256) void mlp_kernel(
    const float* __restrict__ w1,
    const float* __restrict__ b1,
    const float* __restrict__ w2,
    const float* __restrict__ b2,
    float* __restrict__ out,
    int npts)
{
    __shared__ unsigned long long s_w[WIDTH][NPAIR + 1];   // +1 pad
    __shared__ float s_b1[WIDTH];
    __shared__ float s_w2[WIDTH];
    __shared__ float s_b2;

    for (int e = threadIdx.x; e < WIDTH * NPAIR; e += 256) {
        int j = e / NPAIR, i = e % NPAIR;
        float lo = w1[j * IN_MLP + 2 * i];
        float hi = (2 * i + 1 < IN_MLP) ? w1[j * IN_MLP + 2 * i + 1] : 0.0f;
        s_w[j][i] = pack2(lo, hi);
    }
    if (threadIdx.x < WIDTH) {
        s_b1[threadIdx.x] = b1[threadIdx.x];
        s_w2[threadIdx.x] = w2[threadIdx.x];
    }
    if (threadIdx.x == 0) s_b2 = b2[0];
    __syncthreads();

    int n = blockIdx.x * 256 + threadIdx.x;
    if (n >= npts) return;

    unsigned long long h2[NPAIR];
    {
        const float4* fb = reinterpret_cast<const float4*>(g_feat) + n * 4;
        #pragma unroll
        for (int g = 0; g < 4; g++) {
            float4 v = fb[g];
            h2[g * 2 + 0] = pack2(v.x, v.y);
            h2[g * 2 + 1] = pack2(v.z, v.w);
        }
    }
    float4 xp = g_xs[n];
    {
        const float TWO_PI = 6.283185307179586f;
        float p[9];
        float xyz[3] = {xp.x, xp.y, xp.z};
        #pragma unroll
        for (int d = 0; d < 3; d++) {
            float u = xyz[d] * 127.0f;
            float t = u - floorf(u);
            #pragma unroll
            for (int k = 0; k < NUM_POS; k++)
                p[k * 3 + d] = __sinf(TWO_PI * (float)(k + 1) * t);
        }
        h2[8]  = pack2(p[0], p[1]);
        h2[9]  = pack2(p[2], p[3]);
        h2[10] = pack2(p[4], p[5]);
        h2[11] = pack2(p[6], p[7]);
        h2[12] = pack2(p[8], 0.0f);
    }

    float acc = s_b2;
    #pragma unroll 4
    for (int j = 0; j < WIDTH; j++) {
        const unsigned long long* wrow = s_w[j];
        unsigned long long s2 = pack2(0.0f, 0.0f);
        #pragma unroll
        for (int i = 0; i < NPAIR; i++)
            s2 = fma2(wrow[i], h2[i], s2);
        float lo, hi;
        unpack2(s2, lo, hi);
        float s = lo + hi + s_b1[j];
        float g = s * __fdividef(1.0f, 1.0f + __expf(-s));  // swish
        acc += s_w2[j] * g;
    }
    out[__float_as_int(xp.w)] = acc;
}

extern "C" void kernel_launch(void* const* d_in, const int* in_sizes, int n_in,
                              void* d_out, int out_size) {
    const float* x    = (const float*)d_in[0];
    const float* grid = (const float*)d_in[1];
    const float* w1   = (const float*)d_in[2];
    const float* b1   = (const float*)d_in[3];
    const float* w2   = (const float*)d_in[4];
    const float* b2   = (const float*)d_in[5];
    float* out = (float*)d_out;

    int npts = in_sizes[0] / 3;
    if (npts > MAX_PTS) npts = MAX_PTS;

    zero_hist_kernel<<<NB / 256, 256>>>();
    int pblocks = (npts + 255) / 256;
    hist_kernel<<<pblocks, 256>>>(x, npts);
    scan_kernel<<<1, 1024>>>();
    scatter_kernel<<<pblocks, 256>>>(x, npts);

    gather_kernel<<<GATHER_BLOCKS, 512>>>(grid);

    int mblocks = (npts + 255) / 256;
    mlp_kernel<<<mblocks, 256>>>(w1, b1, w2, b2, out, npts);
}